// round 4
// baseline (speedup 1.0000x reference)
#include <cuda_runtime.h>
#include <math.h>

static constexpr int V   = 2048;
static constexpr int VM1 = 2047;
static constexpr float PPROB    = 0.1f;
static constexpr float INV_VM2  = 1.0f / 2046.0f;
static constexpr float LOG_KEEP = -0.10536051565782628f;  // ln(0.9)
static constexpr float LOG_REP  = -9.9262269f;            // ln(0.1/2046)

__global__ __launch_bounds__(256)
void sym_channel_kernel(const float* __restrict__ msgs,
                        const float* __restrict__ logits,
                        const float* __restrict__ noise,
                        float* __restrict__ out,
                        int nrows)
{
    __shared__ float sm_tb[2][512];
    __shared__ float warp_sums[2][8];

    const int tid = threadIdx.x;
    const size_t N = (size_t)nrows * V;
    const int rbase = blockIdx.x * 2;

    size_t rowoff[2];
    rowoff[0] = (size_t)rbase * V;
    rowoff[1] = rowoff[0] + V;

    // ---- front-batch ALL global loads for both rows (max MLP, one mem phase) ----
    float4 mv[2][2], lv[2][2];
    float  l0[2];
    float  nz[2][8];
    #pragma unroll
    for (int rr = 0; rr < 2; rr++) {
        const float4* m4 = reinterpret_cast<const float4*>(msgs + rowoff[rr]);
        const float4* l4 = reinterpret_cast<const float4*>(logits + rowoff[rr]);
        const float* nrow = noise + (size_t)(rbase + rr) * VM1;
        mv[rr][0] = __ldcs(&m4[tid]);
        mv[rr][1] = __ldcs(&m4[tid + 256]);
        lv[rr][0] = __ldcs(&l4[tid]);
        lv[rr][1] = __ldcs(&l4[tid + 256]);
        l0[rr] = __ldg(logits + rowoff[rr]);
        #pragma unroll
        for (int k = 0; k < 2; k++) {
            int base = (tid + k * 256) * 4;
            #pragma unroll
            for (int j = 0; j < 4; j++) {
                int c = base + j;
                nz[rr][k * 4 + j] = (c < VM1) ? __ldcs(&nrow[c]) : 1.0f;
            }
        }
    }

    // ---- verbatim copies (one long store phase) ----
    #pragma unroll
    for (int rr = 0; rr < 2; rr++) {
        float4* out_mc4 = reinterpret_cast<float4*>(out + 2 * N + rowoff[rr]);
        float4* out_lc4 = reinterpret_cast<float4*>(out + 3 * N + rowoff[rr]);
        __stcs(&out_mc4[tid],       mv[rr][0]);
        __stcs(&out_mc4[tid + 256], mv[rr][1]);
        __stcs(&out_lc4[tid],       lv[rr][0]);
        __stcs(&out_lc4[tid + 256], lv[rr][1]);
    }

    // ---- hit masks + local masked sums + boundary t to smem ----
    unsigned msk[2] = {0u, 0u};
    float lsum[2] = {0.0f, 0.0f};
    #pragma unroll
    for (int rr = 0; rr < 2; rr++) {
        #pragma unroll
        for (int k = 0; k < 2; k++) {
            const float* mp = &mv[rr][k].x;
            #pragma unroll
            for (int j = 0; j < 4; j++) {
                if (nz[rr][k * 4 + j] < PPROB) {
                    msk[rr] |= 1u << (k * 4 + j);
                    lsum[rr] += mp[j];
                }
            }
            sm_tb[rr][tid + k * 256] = ((msk[rr] >> (k * 4 + 3)) & 1) ? mp[3] : 0.0f;
        }
    }

    // ---- reduction arrive ----
    #pragma unroll
    for (int rr = 0; rr < 2; rr++) {
        float ws = lsum[rr];
        #pragma unroll
        for (int off = 16; off > 0; off >>= 1)
            ws += __shfl_down_sync(0xFFFFFFFFu, ws, off);
        if ((tid & 31) == 0) warp_sums[rr][tid >> 5] = ws;
    }

    // ---- logits_noisy (independent of barrier; lv dies here) ----
    #pragma unroll
    for (int rr = 0; rr < 2; rr++) {
        float4* out_l4 = reinterpret_cast<float4*>(out + N + rowoff[rr]);
        const float e0 = expf(l0[rr]);
        #pragma unroll
        for (int k = 0; k < 2; k++) {
            int i4 = tid + k * 256;
            const float* lp = &lv[rr][k].x;
            float4 o;
            float* op = &o.x;
            #pragma unroll
            for (int j = 0; j < 4; j++) {
                int jj = i4 * 4 + j;
                if (jj == 0) { op[j] = l0[rr]; continue; }
                float ljv = lp[j];
                float pt = fminf(fmaxf(1.0f - expf(ljv) - e0, 0.0f), 1.0f);
                float a = ljv + LOG_KEEP;
                float b = logf(pt) + LOG_REP;        // logf(0) = -inf is fine
                float mx = fmaxf(a, b);
                float mn = fminf(a, b);
                op[j] = mx + log1pf(expf(mn - mx));  // exp(-inf)=0 -> mx
            }
            __stcs(&out_l4[i4], o);
        }
    }

    __syncthreads();   // covers warp_sums + sm_tb (both rows)

    const float scale = 1.0f + INV_VM2;
    #pragma unroll
    for (int rr = 0; rr < 2; rr++) {
        float row_sum = 0.0f;
        #pragma unroll
        for (int w = 0; w < 8; w++) row_sum += warp_sums[rr][w];
        const float add_c = row_sum * INV_VM2;

        float4* out_m4 = reinterpret_cast<float4*>(out + rowoff[rr]);
        #pragma unroll
        for (int k = 0; k < 2; k++) {
            int i4 = tid + k * 256;
            const float* mp = &mv[rr][k].x;
            float4 o;
            float* op = &o.x;
            #pragma unroll
            for (int j = 0; j < 4; j++) {
                float tprev;
                if (j == 0) {
                    tprev = (i4 == 0) ? 0.0f : sm_tb[rr][i4 - 1];
                } else {
                    tprev = ((msk[rr] >> (k * 4 + j - 1)) & 1) ? mp[j - 1] : 0.0f;
                }
                float val = mp[j];
                if (i4 * 4 + j > 0) val += add_c - tprev * scale;
                op[j] = val;
            }
            __stcs(&out_m4[i4], o);
        }
    }
}

extern "C" void kernel_launch(void* const* d_in, const int* in_sizes, int n_in,
                              void* d_out, int out_size)
{
    const float* msgs   = (const float*)d_in[0];
    const float* logits = (const float*)d_in[1];
    const float* noise  = (const float*)d_in[2];
    float* out = (float*)d_out;
    int nrows = in_sizes[0] / V;   // 16384 (even)
    sym_channel_kernel<<<nrows / 2, 256>>>(msgs, logits, noise, out, nrows);
}